// round 10
// baseline (speedup 1.0000x reference)
#include <cuda_runtime.h>
#include <cstdint>
#include <math.h>

#define TB 8192      // tokens = B*S
#define HD 1024
#define NE 8
#define FF 4096

// GEMM tiling: CTA 128x128, 4 warps (2x2), warptile 64x64
#define GT 128       // GEMM threads per CTA
#define BM 128
#define BN 128
#define KC 32
#define STAGES 3
#define ASTRIDE 36   // floats; frag-read bank = 4*lr + lc  (conflict-free)
#define BSTRIDE 136  // floats (128 data + 8 pad); frag-read bank = 8*lc + lr (conflict-free)

#define A_STG_F (BM * ASTRIDE)            // 4608 floats
#define B_STG_F (KC * BSTRIDE)            // 4352 floats
#define A_BYTES (STAGES * A_STG_F * 4)    // 55296
#define B_BYTES (STAGES * B_STG_F * 4)    // 52224
#define SMEM_SZ (A_BYTES + B_BYTES + 2048) // 109568 -> 2 CTA/SM

// ---- scratch (static device arrays; no allocation) ----
__device__ float g_x [(size_t)TB * HD];        // tf32-rounded x (written by router)
__device__ float g_w1[(size_t)NE * HD * FF];   // tf32-rounded W1
__device__ float g_w2[(size_t)NE * FF * HD];   // tf32-rounded W2
__device__ float g_h [(size_t)2 * TB * FF];    // gelu(x@W1) per slot (tf32-rounded)
__device__ int   g_cnt[NE];
__device__ int   g_tok[NE * TB];
__device__ int   g_slot[NE * TB];
__device__ float g_p0[TB];

// ---- helpers ----
__device__ __forceinline__ uint32_t smem_u32(const void* p) {
    uint32_t a;
    asm("{ .reg .u64 t; cvta.to.shared.u64 t, %1; cvt.u32.u64 %0, t; }" : "=r"(a) : "l"(p));
    return a;
}
__device__ __forceinline__ uint32_t f2tf32(float x) {
    uint32_t u;
    asm("cvt.rna.tf32.f32 %0, %1;" : "=r"(u) : "f"(x));
    return u;
}
__device__ __forceinline__ void cp16(uint32_t s, const void* g) {
    asm volatile("cp.async.cg.shared.global [%0], [%1], 16;" :: "r"(s), "l"(g));
}
#define CP_COMMIT() asm volatile("cp.async.commit_group;" ::: "memory")
#define CP_WAIT1()  asm volatile("cp.async.wait_group 1;" ::: "memory")

#define MMA_TF32(d, a, b) \
    asm volatile("mma.sync.aligned.m16n8k8.row.col.f32.tf32.tf32.f32 " \
        "{%0,%1,%2,%3}, {%4,%5,%6,%7}, {%8,%9}, {%0,%1,%2,%3};" \
        : "+f"((d)[0]), "+f"((d)[1]), "+f"((d)[2]), "+f"((d)[3]) \
        : "r"((a)[0]), "r"((a)[1]), "r"((a)[2]), "r"((a)[3]), \
          "r"((b)[0]), "r"((b)[1]))

__device__ __forceinline__ float fgelu(float v) {
    float z = 0.7978845608028654f * (v + 0.044715f * v * v * v);
    float e = __expf(2.0f * z);
    float t = 1.0f - 2.0f / (e + 1.0f);   // tanh(z)
    return 0.5f * v * (1.0f + t);
}

// ---------------------------------------------------------------------------
// Zero output + expert counters
// ---------------------------------------------------------------------------
__global__ void k_zero(float* __restrict__ out, int n4) {
    int i = blockIdx.x * blockDim.x + threadIdx.x;
    float4 z = make_float4(0.f, 0.f, 0.f, 0.f);
    for (int j = i; j < n4; j += gridDim.x * blockDim.x)
        ((float4*)out)[j] = z;
    if (i < NE) g_cnt[i] = 0;
}

// tf32-round a tensor (float4 grid-stride)
__global__ void k_cvt(const float* __restrict__ src, float* __restrict__ dst, int n4) {
    int i = blockIdx.x * blockDim.x + threadIdx.x;
    for (int j = i; j < n4; j += gridDim.x * blockDim.x) {
        float4 v = ((const float4*)src)[j];
        uint4 u;
        u.x = f2tf32(v.x); u.y = f2tf32(v.y);
        u.z = f2tf32(v.z); u.w = f2tf32(v.w);
        ((uint4*)dst)[j] = u;
    }
}

// ---------------------------------------------------------------------------
// Router (also writes tf32-rounded x into g_x)
// ---------------------------------------------------------------------------
__global__ void k_router(const float* __restrict__ x,
                         const float* __restrict__ Wr,
                         const float* __restrict__ br) {
    int warp = (blockIdx.x * blockDim.x + threadIdx.x) >> 5;
    int lane = threadIdx.x & 31;
    if (warp >= TB) return;
    const float* xr = x + (size_t)warp * HD;
    uint32_t* gxr = (uint32_t*)g_x + (size_t)warp * HD;

    float acc[NE];
#pragma unroll
    for (int e = 0; e < NE; e++) acc[e] = 0.f;
    for (int h = lane; h < HD; h += 32) {
        float xv = xr[h];
        gxr[h] = f2tf32(xv);
        float4 w0 = *(const float4*)(Wr + h * NE);
        float4 w1 = *(const float4*)(Wr + h * NE + 4);
        acc[0] += xv * w0.x; acc[1] += xv * w0.y;
        acc[2] += xv * w0.z; acc[3] += xv * w0.w;
        acc[4] += xv * w1.x; acc[5] += xv * w1.y;
        acc[6] += xv * w1.z; acc[7] += xv * w1.w;
    }
#pragma unroll
    for (int e = 0; e < NE; e++)
#pragma unroll
        for (int off = 16; off > 0; off >>= 1)
            acc[e] += __shfl_xor_sync(0xffffffffu, acc[e], off);
    if (lane == 0) {
#pragma unroll
        for (int e = 0; e < NE; e++) acc[e] += br[e];
        int i1 = 0; float l1 = acc[0];
#pragma unroll
        for (int e = 1; e < NE; e++) if (acc[e] > l1) { l1 = acc[e]; i1 = e; }
        int i2 = -1; float l2 = -3.0e38f;
#pragma unroll
        for (int e = 0; e < NE; e++) if (e != i1 && acc[e] > l2) { l2 = acc[e]; i2 = e; }
        g_p0[warp] = 1.0f / (1.0f + expf(l2 - l1));
        int p = atomicAdd(&g_cnt[i1], 1);
        g_tok[i1 * TB + p]  = warp;
        g_slot[i1 * TB + p] = 2 * warp;
        p = atomicAdd(&g_cnt[i2], 1);
        g_tok[i2 * TB + p]  = warp;
        g_slot[i2 * TB + p] = 2 * warp + 1;
    }
}

// ---------------------------------------------------------------------------
// Grouped GEMM on mma.sync tf32. 128 threads, 4 warps (2x2), warptile 64x64.
// Weights pre-rounded to tf32 (g_w1/g_w2). Register double-buffered fragments.
// MODE 0: g_h[slot] = tf32(gelu(x[tok] @ W1[e] + b1[e]))        (K=HD, N over FF)
// MODE 1: out[tok] += p0 * (g_h[slot] @ W2[e] + b2[e])  (atomic) (K=FF, N over HD)
// ---------------------------------------------------------------------------
template <int MODE>
__global__ __launch_bounds__(GT, 2)
void k_gemm(const float* __restrict__ W, const float* __restrict__ bias,
            float* __restrict__ outp) {
    constexpr int KTOT = MODE ? FF : HD;
    constexpr int LDA  = MODE ? FF : HD;
    constexpr int WROW = MODE ? HD : FF;
    constexpr int OROW = MODE ? HD : FF;
    constexpr int NC   = KTOT / KC;

    const int e  = blockIdx.z;
    const int me = g_cnt[e];
    const int mt = blockIdx.y;
    if (mt * BM >= me) return;
    const int ntb = blockIdx.x * BN;

    extern __shared__ char smraw[];
    float* As = (float*)smraw;
    float* Bs = (float*)(smraw + A_BYTES);
    int*   stok  = (int*)(smraw + A_BYTES + B_BYTES);
    int*   sslot = stok + 128;
    float* sp0   = (float*)(sslot + 128);

    const int tid  = threadIdx.x;
    const int wid  = tid >> 5;
    const int lane = tid & 31;
    const int wm   = wid >> 1;       // 0..1
    const int wn   = wid & 1;        // 0..1
    const int lr   = lane >> 2;      // 0..7  (groupID)
    const int lc   = lane & 3;       // 0..3  (threadID_in_group)

    // token/slot lists (128 rows, 128 threads)
    {
        int i = mt * BM + tid;
        int tok = 0, slot = -1;
        if (i < me) { tok = g_tok[e * TB + i]; slot = g_slot[e * TB + i]; }
        stok[tid] = tok; sslot[tid] = slot;
        if (MODE == 1) sp0[tid] = g_p0[tok];
    }
    __syncthreads();

    // ---- cp.async mappings ----
    const float* Asrc = MODE ? (const float*)g_h : (const float*)g_x;
    const float* aptr[8];
#pragma unroll
    for (int m = 0; m < 8; m++) {
        int row = (tid >> 3) + 16 * m;
        int rid = MODE ? sslot[row] : stok[row];
        if (rid < 0) rid = 0;
        aptr[m] = Asrc + (size_t)rid * LDA + (tid & 7) * 4;
    }
    const uint32_t asmA = smem_u32(As) +
        (uint32_t)((tid >> 3) * ASTRIDE + (tid & 7) * 4) * 4;

    const int bkr = tid >> 2;
    const float* bglob = W + (size_t)e * HD * FF + (size_t)bkr * WROW + ntb + (tid & 3) * 4;
    const uint32_t bsmB = smem_u32(Bs) +
        (uint32_t)(bkr * BSTRIDE + (tid & 3) * 4) * 4;

#define LOAD_CHUNK(STG, C)                                                    \
    {                                                                         \
        uint32_t as_ = asmA + (STG) * (A_STG_F * 4);                          \
        _Pragma("unroll")                                                     \
        for (int m = 0; m < 8; m++)                                           \
            cp16(as_ + m * (16 * ASTRIDE * 4), aptr[m] + (C) * KC);           \
        const float* bg = bglob + (size_t)(C) * KC * WROW;                    \
        uint32_t bs_ = bsmB + (STG) * (B_STG_F * 4);                          \
        _Pragma("unroll")                                                     \
        for (int m = 0; m < 8; m++)                                           \
            cp16(bs_ + m * 64, bg + m * 16);                                  \
    }

// fragment load for k8 step CK into buffer slot BUF
#define LOAD_FRAGS(BUF, CK)                                                   \
    {                                                                         \
        _Pragma("unroll")                                                     \
        for (int i = 0; i < 4; i++) {                                         \
            af[BUF][i][0] = Au[(16 * i) * ASTRIDE + (CK)];                    \
            af[BUF][i][1] = Au[(16 * i + 8) * ASTRIDE + (CK)];                \
            af[BUF][i][2] = Au[(16 * i) * ASTRIDE + (CK) + 4];                \
            af[BUF][i][3] = Au[(16 * i + 8) * ASTRIDE + (CK) + 4];            \
        }                                                                     \
        _Pragma("unroll")                                                     \
        for (int j = 0; j < 8; j++) {                                         \
            bf[BUF][j][0] = Bu[(CK) * BSTRIDE + 8 * j];                       \
            bf[BUF][j][1] = Bu[((CK) + 4) * BSTRIDE + 8 * j];                 \
        }                                                                     \
    }

    float acc[4][8][4];
#pragma unroll
    for (int i = 0; i < 4; i++)
#pragma unroll
        for (int j = 0; j < 8; j++)
#pragma unroll
            for (int r = 0; r < 4; r++) acc[i][j][r] = 0.f;

    LOAD_CHUNK(0, 0); CP_COMMIT();
    LOAD_CHUNK(1, 1); CP_COMMIT();

    const uint32_t* Au0 = (const uint32_t*)As + (wm * 64 + lr) * ASTRIDE + lc;
    const uint32_t* Bu0 = (const uint32_t*)Bs + lc * BSTRIDE + wn * 64 + lr;

    for (int c = 0; c < NC; c++) {
        // Wait for chunk c's data, one barrier, then issue loads for c+2.
        CP_WAIT1();
        __syncthreads();
        const int pf = c + STAGES - 1;
        if (pf < NC) { LOAD_CHUNK(pf % STAGES, pf); }
        CP_COMMIT();

        const int st = c % STAGES;
        const uint32_t* Au = Au0 + st * A_STG_F;
        const uint32_t* Bu = Bu0 + st * B_STG_F;

        uint32_t af[2][4][4], bf[2][8][2];
        LOAD_FRAGS(0, 0);
#pragma unroll
        for (int k8 = 0; k8 < KC / 8; k8++) {
            const int cur = k8 & 1;
            if (k8 + 1 < KC / 8) {
                const int ck = (k8 + 1) * 8;
                LOAD_FRAGS(cur ^ 1, ck);
            }
#pragma unroll
            for (int i = 0; i < 4; i++)
#pragma unroll
                for (int j = 0; j < 8; j++)
                    MMA_TF32(acc[i][j], af[cur][i], bf[cur][j]);
        }
    }

    // ---- epilogue ----
    float bv[16];
#pragma unroll
    for (int j = 0; j < 8; j++) {
        float2 t = *(const float2*)(bias + e * OROW + ntb + wn * 64 + 8 * j + lc * 2);
        bv[2 * j] = t.x; bv[2 * j + 1] = t.y;
    }

#pragma unroll
    for (int i = 0; i < 4; i++) {
        const int mr0 = wm * 64 + 16 * i + lr;
        const int s0 = sslot[mr0];
        const int s1 = sslot[mr0 + 8];
#pragma unroll
        for (int j = 0; j < 8; j++) {
            const int n = ntb + wn * 64 + 8 * j + lc * 2;
            if (MODE == 0) {
                if (s0 >= 0) {
                    float2 v;
                    v.x = __uint_as_float(f2tf32(fgelu(acc[i][j][0] + bv[2 * j])));
                    v.y = __uint_as_float(f2tf32(fgelu(acc[i][j][1] + bv[2 * j + 1])));
                    *(float2*)(g_h + (size_t)s0 * OROW + n) = v;
                }
                if (s1 >= 0) {
                    float2 v;
                    v.x = __uint_as_float(f2tf32(fgelu(acc[i][j][2] + bv[2 * j])));
                    v.y = __uint_as_float(f2tf32(fgelu(acc[i][j][3] + bv[2 * j + 1])));
                    *(float2*)(g_h + (size_t)s1 * OROW + n) = v;
                }
            } else {
                if (s0 >= 0) {
                    float p = sp0[mr0];
                    float* op = outp + (size_t)stok[mr0] * HD + n;
                    atomicAdd(op,     p * (acc[i][j][0] + bv[2 * j]));
                    atomicAdd(op + 1, p * (acc[i][j][1] + bv[2 * j + 1]));
                }
                if (s1 >= 0) {
                    float p = sp0[mr0 + 8];
                    float* op = outp + (size_t)stok[mr0 + 8] * HD + n;
                    atomicAdd(op,     p * (acc[i][j][2] + bv[2 * j]));
                    atomicAdd(op + 1, p * (acc[i][j][3] + bv[2 * j + 1]));
                }
            }
        }
    }
}

// ---------------------------------------------------------------------------
extern "C" void kernel_launch(void* const* d_in, const int* in_sizes, int n_in,
                              void* d_out, int out_size) {
    const float* x  = (const float*)d_in[0];
    const float* Wr = (const float*)d_in[1];
    const float* br = (const float*)d_in[2];
    const float* W1 = (const float*)d_in[3];
    const float* b1 = (const float*)d_in[4];
    const float* W2 = (const float*)d_in[5];
    const float* b2 = (const float*)d_in[6];
    float* out = (float*)d_out;

    cudaFuncSetAttribute(k_gemm<0>, cudaFuncAttributeMaxDynamicSharedMemorySize, SMEM_SZ);
    cudaFuncSetAttribute(k_gemm<1>, cudaFuncAttributeMaxDynamicSharedMemorySize, SMEM_SZ);

    float* gw1; cudaGetSymbolAddress((void**)&gw1, g_w1);
    float* gw2; cudaGetSymbolAddress((void**)&gw2, g_w2);

    k_zero<<<2048, 256>>>(out, out_size / 4);
    k_router<<<TB / 8, 256>>>(x, Wr, br);
    k_cvt<<<8192, 256>>>(W1, gw1, NE * HD * FF / 4);
    k_cvt<<<8192, 256>>>(W2, gw2, NE * FF * HD / 4);
    dim3 g1(FF / BN, TB / BM, NE);   // (32, 64, 8)
    k_gemm<0><<<g1, GT, SMEM_SZ>>>(gw1, b1, nullptr);
    dim3 g2(HD / BN, TB / BM, NE);   // (8, 64, 8)
    k_gemm<1><<<g2, GT, SMEM_SZ>>>(gw2, b2, out);
}

// round 11
// speedup vs baseline: 1.0441x; 1.0441x over previous
#include <cuda_runtime.h>
#include <cstdint>
#include <math.h>

#define TB 8192      // tokens = B*S
#define HD 1024
#define NE 8
#define FF 4096

// GEMM tiling: CTA 128x128, 4 warps (2x2), warptile 64x64  (R8 core)
#define GT 128       // GEMM threads per CTA
#define BM 128
#define BN 128
#define KC 32
#define STAGES 3
#define ASTRIDE 36   // floats; frag-read bank = 4*lr + lc  (conflict-free)
#define BSTRIDE 136  // floats (128 data + 8 pad); frag-read bank = 8*lc + lr (conflict-free)

// Systematic tf32-truncation bias compensation: trunc(w) = w*(1-delta),
// E[delta] = 2^-11 * E[1/mantissa] ~= 3.4e-4..4.0e-4 (measured-implied 3.96e-4).
#define TRUNC_SCALE 1.00037f

#define A_STG_F (BM * ASTRIDE)            // 4608 floats
#define B_STG_F (KC * BSTRIDE)            // 4352 floats
#define A_BYTES (STAGES * A_STG_F * 4)    // 55296
#define B_BYTES (STAGES * B_STG_F * 4)    // 52224
#define SMEM_SZ (A_BYTES + B_BYTES + 2048) // 109568 -> 2 CTA/SM

// ---- scratch (static device arrays; no allocation) ----
__device__ float g_x [(size_t)TB * HD];        // tf32-rounded x (written by router)
__device__ float g_h [(size_t)2 * TB * FF];    // gelu(x@W1) per slot (tf32-rounded)
__device__ int   g_cnt[NE];
__device__ int   g_tok[NE * TB];
__device__ int   g_slot[NE * TB];
__device__ float g_p0[TB];

// ---- helpers ----
__device__ __forceinline__ uint32_t smem_u32(const void* p) {
    uint32_t a;
    asm("{ .reg .u64 t; cvta.to.shared.u64 t, %1; cvt.u32.u64 %0, t; }" : "=r"(a) : "l"(p));
    return a;
}
__device__ __forceinline__ uint32_t f2tf32(float x) {
    uint32_t u;
    asm("cvt.rna.tf32.f32 %0, %1;" : "=r"(u) : "f"(x));
    return u;
}
__device__ __forceinline__ void cp16(uint32_t s, const void* g) {
    asm volatile("cp.async.cg.shared.global [%0], [%1], 16;" :: "r"(s), "l"(g));
}
#define CP_COMMIT() asm volatile("cp.async.commit_group;" ::: "memory")
#define CP_WAIT2()  asm volatile("cp.async.wait_group 2;" ::: "memory")

#define MMA_TF32(d, a, b) \
    asm volatile("mma.sync.aligned.m16n8k8.row.col.f32.tf32.tf32.f32 " \
        "{%0,%1,%2,%3}, {%4,%5,%6,%7}, {%8,%9}, {%0,%1,%2,%3};" \
        : "+f"((d)[0]), "+f"((d)[1]), "+f"((d)[2]), "+f"((d)[3]) \
        : "r"((a)[0]), "r"((a)[1]), "r"((a)[2]), "r"((a)[3]), \
          "r"((b)[0]), "r"((b)[1]))

__device__ __forceinline__ float fgelu(float v) {
    float z = 0.7978845608028654f * (v + 0.044715f * v * v * v);
    float e = __expf(2.0f * z);
    float t = 1.0f - 2.0f / (e + 1.0f);   // tanh(z)
    return 0.5f * v * (1.0f + t);
}

// ---------------------------------------------------------------------------
// Zero output + expert counters
// ---------------------------------------------------------------------------
__global__ void k_zero(float* __restrict__ out, int n4) {
    int i = blockIdx.x * blockDim.x + threadIdx.x;
    float4 z = make_float4(0.f, 0.f, 0.f, 0.f);
    for (int j = i; j < n4; j += gridDim.x * blockDim.x)
        ((float4*)out)[j] = z;
    if (i < NE) g_cnt[i] = 0;
}

// ---------------------------------------------------------------------------
// Router (also writes tf32-rounded x into g_x)
// ---------------------------------------------------------------------------
__global__ void k_router(const float* __restrict__ x,
                         const float* __restrict__ Wr,
                         const float* __restrict__ br) {
    int warp = (blockIdx.x * blockDim.x + threadIdx.x) >> 5;
    int lane = threadIdx.x & 31;
    if (warp >= TB) return;
    const float* xr = x + (size_t)warp * HD;
    uint32_t* gxr = (uint32_t*)g_x + (size_t)warp * HD;

    float acc[NE];
#pragma unroll
    for (int e = 0; e < NE; e++) acc[e] = 0.f;
    for (int h = lane; h < HD; h += 32) {
        float xv = xr[h];
        gxr[h] = f2tf32(xv);
        float4 w0 = *(const float4*)(Wr + h * NE);
        float4 w1 = *(const float4*)(Wr + h * NE + 4);
        acc[0] += xv * w0.x; acc[1] += xv * w0.y;
        acc[2] += xv * w0.z; acc[3] += xv * w0.w;
        acc[4] += xv * w1.x; acc[5] += xv * w1.y;
        acc[6] += xv * w1.z; acc[7] += xv * w1.w;
    }
#pragma unroll
    for (int e = 0; e < NE; e++)
#pragma unroll
        for (int off = 16; off > 0; off >>= 1)
            acc[e] += __shfl_xor_sync(0xffffffffu, acc[e], off);
    if (lane == 0) {
#pragma unroll
        for (int e = 0; e < NE; e++) acc[e] += br[e];
        int i1 = 0; float l1 = acc[0];
#pragma unroll
        for (int e = 1; e < NE; e++) if (acc[e] > l1) { l1 = acc[e]; i1 = e; }
        int i2 = -1; float l2 = -3.0e38f;
#pragma unroll
        for (int e = 0; e < NE; e++) if (e != i1 && acc[e] > l2) { l2 = acc[e]; i2 = e; }
        g_p0[warp] = 1.0f / (1.0f + expf(l2 - l1));
        int p = atomicAdd(&g_cnt[i1], 1);
        g_tok[i1 * TB + p]  = warp;
        g_slot[i1 * TB + p] = 2 * warp;
        p = atomicAdd(&g_cnt[i2], 1);
        g_tok[i2 * TB + p]  = warp;
        g_slot[i2 * TB + p] = 2 * warp + 1;
    }
}

// ---------------------------------------------------------------------------
// Grouped GEMM on mma.sync tf32. 128 threads, 4 warps (2x2), warptile 64x64.
// W fed raw fp32 (HW truncates to tf32); systematic truncation bias removed
// by TRUNC_SCALE in the epilogue. A-side operands are RNA-rounded.
// MODE 0: g_h[slot] = tf32(gelu(s*(x[tok] @ W1[e]) + b1[e]))     (K=HD, N over FF)
// MODE 1: out[tok] += p0 * (s*(g_h[slot] @ W2[e]) + b2[e])       (K=FF, N over HD)
// ---------------------------------------------------------------------------
template <int MODE>
__global__ __launch_bounds__(GT, 2)
void k_gemm(const float* __restrict__ W, const float* __restrict__ bias,
            float* __restrict__ outp) {
    constexpr int KTOT = MODE ? FF : HD;
    constexpr int LDA  = MODE ? FF : HD;
    constexpr int WROW = MODE ? HD : FF;
    constexpr int OROW = MODE ? HD : FF;
    constexpr int NC   = KTOT / KC;

    const int e  = blockIdx.z;
    const int me = g_cnt[e];
    const int mt = blockIdx.y;
    if (mt * BM >= me) return;
    const int ntb = blockIdx.x * BN;

    extern __shared__ char smraw[];
    float* As = (float*)smraw;
    float* Bs = (float*)(smraw + A_BYTES);
    int*   stok  = (int*)(smraw + A_BYTES + B_BYTES);
    int*   sslot = stok + 128;
    float* sp0   = (float*)(sslot + 128);

    const int tid  = threadIdx.x;
    const int wid  = tid >> 5;
    const int lane = tid & 31;
    const int wm   = wid >> 1;       // 0..1
    const int wn   = wid & 1;        // 0..1
    const int lr   = lane >> 2;      // 0..7  (groupID)
    const int lc   = lane & 3;       // 0..3  (threadID_in_group)

    // token/slot lists (128 rows, 128 threads)
    {
        int i = mt * BM + tid;
        int tok = 0, slot = -1;
        if (i < me) { tok = g_tok[e * TB + i]; slot = g_slot[e * TB + i]; }
        stok[tid] = tok; sslot[tid] = slot;
        if (MODE == 1) sp0[tid] = g_p0[tok];
    }
    __syncthreads();

    // ---- cp.async mappings ----
    const float* Asrc = MODE ? (const float*)g_h : (const float*)g_x;
    const float* aptr[8];
#pragma unroll
    for (int m = 0; m < 8; m++) {
        int row = (tid >> 3) + 16 * m;
        int rid = MODE ? sslot[row] : stok[row];
        if (rid < 0) rid = 0;
        aptr[m] = Asrc + (size_t)rid * LDA + (tid & 7) * 4;
    }
    const uint32_t asmA = smem_u32(As) +
        (uint32_t)((tid >> 3) * ASTRIDE + (tid & 7) * 4) * 4;

    const int bkr = tid >> 2;
    const float* bglob = W + (size_t)e * HD * FF + (size_t)bkr * WROW + ntb + (tid & 3) * 4;
    const uint32_t bsmB = smem_u32(Bs) +
        (uint32_t)(bkr * BSTRIDE + (tid & 3) * 4) * 4;

#define LOAD_CHUNK(STG, C)                                                    \
    {                                                                         \
        uint32_t as_ = asmA + (STG) * (A_STG_F * 4);                          \
        _Pragma("unroll")                                                     \
        for (int m = 0; m < 8; m++)                                           \
            cp16(as_ + m * (16 * ASTRIDE * 4), aptr[m] + (C) * KC);           \
        const float* bg = bglob + (size_t)(C) * KC * WROW;                    \
        uint32_t bs_ = bsmB + (STG) * (B_STG_F * 4);                          \
        _Pragma("unroll")                                                     \
        for (int m = 0; m < 8; m++)                                           \
            cp16(bs_ + m * 64, bg + m * 16);                                  \
    }

    float acc[4][8][4];
#pragma unroll
    for (int i = 0; i < 4; i++)
#pragma unroll
        for (int j = 0; j < 8; j++)
#pragma unroll
            for (int r = 0; r < 4; r++) acc[i][j][r] = 0.f;

    LOAD_CHUNK(0, 0); CP_COMMIT();
    LOAD_CHUNK(1, 1); CP_COMMIT();

    const uint32_t* Au0 = (const uint32_t*)As + (wm * 64 + lr) * ASTRIDE + lc;
    const uint32_t* Bu0 = (const uint32_t*)Bs + lc * BSTRIDE + wn * 64 + lr;

    for (int c = 0; c < NC; c++) {
        const int pf = c + STAGES - 1;
        if (pf < NC) { LOAD_CHUNK(pf % STAGES, pf); }
        CP_COMMIT();
        CP_WAIT2();
        __syncthreads();

        const int st = c % STAGES;
        const uint32_t* Au = Au0 + st * A_STG_F;
        const uint32_t* Bu = Bu0 + st * B_STG_F;
#pragma unroll
        for (int k8 = 0; k8 < KC / 8; k8++) {
            const int ck = k8 * 8;
            uint32_t af[4][4], bf[8][2];
#pragma unroll
            for (int i = 0; i < 4; i++) {
                af[i][0] = Au[(16 * i) * ASTRIDE + ck];
                af[i][1] = Au[(16 * i + 8) * ASTRIDE + ck];
                af[i][2] = Au[(16 * i) * ASTRIDE + ck + 4];
                af[i][3] = Au[(16 * i + 8) * ASTRIDE + ck + 4];
            }
#pragma unroll
            for (int j = 0; j < 8; j++) {
                bf[j][0] = Bu[ck * BSTRIDE + 8 * j];
                bf[j][1] = Bu[(ck + 4) * BSTRIDE + 8 * j];
            }
#pragma unroll
            for (int i = 0; i < 4; i++)
#pragma unroll
                for (int j = 0; j < 8; j++)
                    MMA_TF32(acc[i][j], af[i], bf[j]);
        }
        __syncthreads();
    }

    // ---- epilogue (with truncation-bias compensation) ----
    float bv[16];
#pragma unroll
    for (int j = 0; j < 8; j++) {
        float2 t = *(const float2*)(bias + e * OROW + ntb + wn * 64 + 8 * j + lc * 2);
        bv[2 * j] = t.x; bv[2 * j + 1] = t.y;
    }

#pragma unroll
    for (int i = 0; i < 4; i++) {
        const int mr0 = wm * 64 + 16 * i + lr;
        const int s0 = sslot[mr0];
        const int s1 = sslot[mr0 + 8];
#pragma unroll
        for (int j = 0; j < 8; j++) {
            const int n = ntb + wn * 64 + 8 * j + lc * 2;
            if (MODE == 0) {
                if (s0 >= 0) {
                    float2 v;
                    v.x = __uint_as_float(f2tf32(fgelu(TRUNC_SCALE * acc[i][j][0] + bv[2 * j])));
                    v.y = __uint_as_float(f2tf32(fgelu(TRUNC_SCALE * acc[i][j][1] + bv[2 * j + 1])));
                    *(float2*)(g_h + (size_t)s0 * OROW + n) = v;
                }
                if (s1 >= 0) {
                    float2 v;
                    v.x = __uint_as_float(f2tf32(fgelu(TRUNC_SCALE * acc[i][j][2] + bv[2 * j])));
                    v.y = __uint_as_float(f2tf32(fgelu(TRUNC_SCALE * acc[i][j][3] + bv[2 * j + 1])));
                    *(float2*)(g_h + (size_t)s1 * OROW + n) = v;
                }
            } else {
                if (s0 >= 0) {
                    float p = sp0[mr0];
                    float* op = outp + (size_t)stok[mr0] * HD + n;
                    atomicAdd(op,     p * (TRUNC_SCALE * acc[i][j][0] + bv[2 * j]));
                    atomicAdd(op + 1, p * (TRUNC_SCALE * acc[i][j][1] + bv[2 * j + 1]));
                }
                if (s1 >= 0) {
                    float p = sp0[mr0 + 8];
                    float* op = outp + (size_t)stok[mr0 + 8] * HD + n;
                    atomicAdd(op,     p * (TRUNC_SCALE * acc[i][j][2] + bv[2 * j]));
                    atomicAdd(op + 1, p * (TRUNC_SCALE * acc[i][j][3] + bv[2 * j + 1]));
                }
            }
        }
    }
}

// ---------------------------------------------------------------------------
extern "C" void kernel_launch(void* const* d_in, const int* in_sizes, int n_in,
                              void* d_out, int out_size) {
    const float* x  = (const float*)d_in[0];
    const float* Wr = (const float*)d_in[1];
    const float* br = (const float*)d_in[2];
    const float* W1 = (const float*)d_in[3];
    const float* b1 = (const float*)d_in[4];
    const float* W2 = (const float*)d_in[5];
    const float* b2 = (const float*)d_in[6];
    float* out = (float*)d_out;

    cudaFuncSetAttribute(k_gemm<0>, cudaFuncAttributeMaxDynamicSharedMemorySize, SMEM_SZ);
    cudaFuncSetAttribute(k_gemm<1>, cudaFuncAttributeMaxDynamicSharedMemorySize, SMEM_SZ);

    k_zero<<<2048, 256>>>(out, out_size / 4);
    k_router<<<TB / 8, 256>>>(x, Wr, br);
    dim3 g1(FF / BN, TB / BM, NE);   // (32, 64, 8)
    k_gemm<0><<<g1, GT, SMEM_SZ>>>(W1, b1, nullptr);
    dim3 g2(HD / BN, TB / BM, NE);   // (8, 64, 8)
    k_gemm<1><<<g2, GT, SMEM_SZ>>>(W2, b2, out);
}

// round 12
// speedup vs baseline: 1.7459x; 1.6722x over previous
#include <cuda_runtime.h>
#include <cuda_fp16.h>
#include <cstdint>
#include <math.h>

#define TB 8192      // tokens = B*S
#define HD 1024
#define NE 8
#define FF 4096

// GEMM tiling: CTA 128x128, 4 warps (2x2), warptile 64x64, fp16 MMA k16
#define GT 128       // GEMM threads per CTA
#define BM 128
#define BN 128
#define KC 64        // k-elements (halves) per chunk = 128B per row
#define STAGES 3
#define ROWB 144     // SMEM row stride bytes (128 data + 16 pad); bank = 4*lr+lc (conflict-free)
#define ROW_U32 36
#define TSTG (128 * ROWB)                 // 18432 B per tile stage
#define B_OFF (STAGES * TSTG)             // 55296
#define LIST_OFF (2 * STAGES * TSTG)      // 110592
#define SMEM_SZ (LIST_OFF + 2048)         // 112640 -> 2 CTA/SM

// ---- scratch (static device arrays; no allocation) ----
__device__ __half g_xh [(size_t)TB * HD];        // fp16 x (written by router)
__device__ __half g_h  [(size_t)2 * TB * FF];    // fp16 gelu(x@W1) per slot
__device__ __half g_w1h[(size_t)NE * FF * HD];   // W1 transposed [f][h] fp16
__device__ __half g_w2h[(size_t)NE * HD * FF];   // W2 transposed [h][f] fp16
__device__ int   g_cnt[NE];
__device__ int   g_tok[NE * TB];
__device__ int   g_slot[NE * TB];
__device__ float g_p0[TB];

// ---- helpers ----
__device__ __forceinline__ uint32_t smem_u32(const void* p) {
    uint32_t a;
    asm("{ .reg .u64 t; cvta.to.shared.u64 t, %1; cvt.u32.u64 %0, t; }" : "=r"(a) : "l"(p));
    return a;
}
__device__ __forceinline__ void cp16(uint32_t s, const void* g) {
    asm volatile("cp.async.cg.shared.global [%0], [%1], 16;" :: "r"(s), "l"(g));
}
#define CP_COMMIT() asm volatile("cp.async.commit_group;" ::: "memory")
#define CP_WAIT2()  asm volatile("cp.async.wait_group 2;" ::: "memory")

#define MMA_F16(d, a, b) \
    asm volatile("mma.sync.aligned.m16n8k16.row.col.f32.f16.f16.f32 " \
        "{%0,%1,%2,%3}, {%4,%5,%6,%7}, {%8,%9}, {%0,%1,%2,%3};" \
        : "+f"((d)[0]), "+f"((d)[1]), "+f"((d)[2]), "+f"((d)[3]) \
        : "r"((a)[0]), "r"((a)[1]), "r"((a)[2]), "r"((a)[3]), \
          "r"((b)[0]), "r"((b)[1]))

__device__ __forceinline__ float fgelu(float v) {
    float z = 0.7978845608028654f * (v + 0.044715f * v * v * v);
    float e = __expf(2.0f * z);
    float t = 1.0f - 2.0f / (e + 1.0f);   // tanh(z)
    return 0.5f * v * (1.0f + t);
}

// ---------------------------------------------------------------------------
// Zero output + expert counters
// ---------------------------------------------------------------------------
__global__ void k_zero(float* __restrict__ out, int n4) {
    int i = blockIdx.x * blockDim.x + threadIdx.x;
    float4 z = make_float4(0.f, 0.f, 0.f, 0.f);
    for (int j = i; j < n4; j += gridDim.x * blockDim.x)
        ((float4*)out)[j] = z;
    if (i < NE) g_cnt[i] = 0;
}

// ---------------------------------------------------------------------------
// Transpose + convert one expert-stack of weights: [E][K][N] fp32 -> [E][N][K] fp16
// ---------------------------------------------------------------------------
__global__ void k_cvt_t(const float* __restrict__ src, __half* __restrict__ dst,
                        int K, int N) {
    __shared__ float tile[32][33];
    const int e  = blockIdx.z;
    const int nb = blockIdx.x * 32;
    const int kb = blockIdx.y * 32;
    const float* s = src + (size_t)e * K * N;
    __half* d = dst + (size_t)e * K * N;
    const int tid = threadIdx.x;   // 256
#pragma unroll
    for (int p = 0; p < 4; p++) {
        int idx = tid + p * 256;
        int r = idx >> 5, c = idx & 31;
        tile[r][c] = s[(size_t)(kb + r) * N + nb + c];
    }
    __syncthreads();
#pragma unroll
    for (int p = 0; p < 4; p++) {
        int idx = tid + p * 256;
        int r = idx >> 5, c = idx & 31;
        d[(size_t)(nb + r) * K + kb + c] = __float2half_rn(tile[c][r]);
    }
}

// ---------------------------------------------------------------------------
// Router (also writes fp16 x into g_xh)
// ---------------------------------------------------------------------------
__global__ void k_router(const float* __restrict__ x,
                         const float* __restrict__ Wr,
                         const float* __restrict__ br) {
    int warp = (blockIdx.x * blockDim.x + threadIdx.x) >> 5;
    int lane = threadIdx.x & 31;
    if (warp >= TB) return;
    const float* xr = x + (size_t)warp * HD;
    __half* gxr = g_xh + (size_t)warp * HD;

    float acc[NE];
#pragma unroll
    for (int e = 0; e < NE; e++) acc[e] = 0.f;
    for (int h = lane; h < HD; h += 32) {
        float xv = xr[h];
        gxr[h] = __float2half_rn(xv);
        float4 w0 = *(const float4*)(Wr + h * NE);
        float4 w1 = *(const float4*)(Wr + h * NE + 4);
        acc[0] += xv * w0.x; acc[1] += xv * w0.y;
        acc[2] += xv * w0.z; acc[3] += xv * w0.w;
        acc[4] += xv * w1.x; acc[5] += xv * w1.y;
        acc[6] += xv * w1.z; acc[7] += xv * w1.w;
    }
#pragma unroll
    for (int e = 0; e < NE; e++)
#pragma unroll
        for (int off = 16; off > 0; off >>= 1)
            acc[e] += __shfl_xor_sync(0xffffffffu, acc[e], off);
    if (lane == 0) {
#pragma unroll
        for (int e = 0; e < NE; e++) acc[e] += br[e];
        int i1 = 0; float l1 = acc[0];
#pragma unroll
        for (int e = 1; e < NE; e++) if (acc[e] > l1) { l1 = acc[e]; i1 = e; }
        int i2 = -1; float l2 = -3.0e38f;
#pragma unroll
        for (int e = 0; e < NE; e++) if (e != i1 && acc[e] > l2) { l2 = acc[e]; i2 = e; }
        g_p0[warp] = 1.0f / (1.0f + expf(l2 - l1));
        int p = atomicAdd(&g_cnt[i1], 1);
        g_tok[i1 * TB + p]  = warp;
        g_slot[i1 * TB + p] = 2 * warp;
        p = atomicAdd(&g_cnt[i2], 1);
        g_tok[i2 * TB + p]  = warp;
        g_slot[i2 * TB + p] = 2 * warp + 1;
    }
}

// ---------------------------------------------------------------------------
// Grouped GEMM on mma.sync fp16 (fp32 accumulate).
// A: [row][k] fp16 k-contiguous (g_xh or g_h). B: transposed weights [n][k] fp16.
// MODE 0: g_h[slot] = fp16(gelu(x[tok] @ W1[e] + b1[e]))        (K=HD, N over FF)
// MODE 1: out[tok] += p0 * ((g_h[slot] @ W2[e]) + b2[e]) atomic (K=FF, N over HD)
// ---------------------------------------------------------------------------
template <int MODE>
__global__ __launch_bounds__(GT, 2)
void k_gemm(const __half* __restrict__ W, const float* __restrict__ bias,
            float* __restrict__ outp) {
    constexpr int KTOT = MODE ? FF : HD;
    constexpr int LDA  = MODE ? FF : HD;
    constexpr int OROW = MODE ? HD : FF;
    constexpr int NC   = KTOT / KC;

    const int e  = blockIdx.z;
    const int me = g_cnt[e];
    const int mt = blockIdx.y;
    if (mt * BM >= me) return;
    const int ntb = blockIdx.x * BN;

    extern __shared__ char smraw[];
    char* As = smraw;
    char* Bs = smraw + B_OFF;
    int*   stok  = (int*)(smraw + LIST_OFF);
    int*   sslot = stok + 128;
    float* sp0   = (float*)(sslot + 128);

    const int tid  = threadIdx.x;
    const int wid  = tid >> 5;
    const int lane = tid & 31;
    const int wm   = wid >> 1;       // 0..1
    const int wn   = wid & 1;        // 0..1
    const int lr   = lane >> 2;      // 0..7  (groupID)
    const int lc   = lane & 3;       // 0..3  (threadID_in_group)

    {
        int i = mt * BM + tid;
        int tok = 0, slot = -1;
        if (i < me) { tok = g_tok[e * TB + i]; slot = g_slot[e * TB + i]; }
        stok[tid] = tok; sslot[tid] = slot;
        if (MODE == 1) sp0[tid] = g_p0[tok];
    }
    __syncthreads();

    // ---- cp.async mappings ----
    // rows: (tid>>3) + 16*m (m=0..7); 8 lanes cover one 128B row run.
    const int mrow = tid >> 3;            // 0..15
    const int mseg = tid & 7;             // 0..7
    const __half* Asrc = MODE ? (const __half*)g_h : (const __half*)g_xh;
    const __half* aptr[8];
#pragma unroll
    for (int m = 0; m < 8; m++) {
        int row = mrow + 16 * m;
        int rid = MODE ? sslot[row] : stok[row];
        if (rid < 0) rid = 0;
        aptr[m] = Asrc + (size_t)rid * LDA + mseg * 8;
    }
    const uint32_t asmA = smem_u32(As) + (uint32_t)(mrow * ROWB + mseg * 16);

    const __half* bglob = W + (size_t)e * HD * FF + (size_t)(ntb + mrow) * KTOT + mseg * 8;
    const uint32_t bsmB = smem_u32(Bs) + (uint32_t)(mrow * ROWB + mseg * 16);

#define LOAD_CHUNK(STG, C)                                                    \
    {                                                                         \
        uint32_t as_ = asmA + (STG) * TSTG;                                   \
        _Pragma("unroll")                                                     \
        for (int m = 0; m < 8; m++)                                           \
            cp16(as_ + m * (16 * ROWB), aptr[m] + (C) * KC);                  \
        const __half* bg = bglob + (size_t)(C) * KC;                          \
        uint32_t bs_ = bsmB + (STG) * TSTG;                                   \
        _Pragma("unroll")                                                     \
        for (int m = 0; m < 8; m++)                                           \
            cp16(bs_ + m * (16 * ROWB), bg + (size_t)m * 16 * KTOT);          \
    }

    float acc[4][8][4];
#pragma unroll
    for (int i = 0; i < 4; i++)
#pragma unroll
        for (int j = 0; j < 8; j++)
#pragma unroll
            for (int r = 0; r < 4; r++) acc[i][j][r] = 0.f;

    LOAD_CHUNK(0, 0); CP_COMMIT();
    LOAD_CHUNK(1, 1); CP_COMMIT();

    const uint32_t* Au0 = (const uint32_t*)As + (wm * 64 + lr) * ROW_U32 + lc;
    const uint32_t* Bu0 = (const uint32_t*)Bs + (wn * 64 + lr) * ROW_U32 + lc;

    for (int c = 0; c < NC; c++) {
        const int pf = c + STAGES - 1;
        if (pf < NC) { LOAD_CHUNK(pf % STAGES, pf); }
        CP_COMMIT();
        CP_WAIT2();
        __syncthreads();

        const int st = c % STAGES;
        const uint32_t* Au = Au0 + st * (TSTG / 4);
        const uint32_t* Bu = Bu0 + st * (TSTG / 4);
#pragma unroll
        for (int k16 = 0; k16 < KC / 16; k16++) {
            const int ck8 = k16 * 8;     // u32 offset within row
            uint32_t af[4][4], bf[8][2];
#pragma unroll
            for (int i = 0; i < 4; i++) {
                af[i][0] = Au[(16 * i) * ROW_U32 + ck8];
                af[i][1] = Au[(16 * i + 8) * ROW_U32 + ck8];
                af[i][2] = Au[(16 * i) * ROW_U32 + ck8 + 4];
                af[i][3] = Au[(16 * i + 8) * ROW_U32 + ck8 + 4];
            }
#pragma unroll
            for (int j = 0; j < 8; j++) {
                bf[j][0] = Bu[(8 * j) * ROW_U32 + ck8];
                bf[j][1] = Bu[(8 * j) * ROW_U32 + ck8 + 4];
            }
#pragma unroll
            for (int i = 0; i < 4; i++)
#pragma unroll
                for (int j = 0; j < 8; j++)
                    MMA_F16(acc[i][j], af[i], bf[j]);
        }
        __syncthreads();
    }

    // ---- epilogue ----
    float bv[16];
#pragma unroll
    for (int j = 0; j < 8; j++) {
        float2 t = *(const float2*)(bias + e * OROW + ntb + wn * 64 + 8 * j + lc * 2);
        bv[2 * j] = t.x; bv[2 * j + 1] = t.y;
    }

#pragma unroll
    for (int i = 0; i < 4; i++) {
        const int mr0 = wm * 64 + 16 * i + lr;
        const int s0 = sslot[mr0];
        const int s1 = sslot[mr0 + 8];
#pragma unroll
        for (int j = 0; j < 8; j++) {
            const int n = ntb + wn * 64 + 8 * j + lc * 2;
            if (MODE == 0) {
                if (s0 >= 0) {
                    *(__half2*)(g_h + (size_t)s0 * OROW + n) = __floats2half2_rn(
                        fgelu(acc[i][j][0] + bv[2 * j]),
                        fgelu(acc[i][j][1] + bv[2 * j + 1]));
                }
                if (s1 >= 0) {
                    *(__half2*)(g_h + (size_t)s1 * OROW + n) = __floats2half2_rn(
                        fgelu(acc[i][j][2] + bv[2 * j]),
                        fgelu(acc[i][j][3] + bv[2 * j + 1]));
                }
            } else {
                if (s0 >= 0) {
                    float p = sp0[mr0];
                    float* op = outp + (size_t)stok[mr0] * HD + n;
                    atomicAdd(op,     p * (acc[i][j][0] + bv[2 * j]));
                    atomicAdd(op + 1, p * (acc[i][j][1] + bv[2 * j + 1]));
                }
                if (s1 >= 0) {
                    float p = sp0[mr0 + 8];
                    float* op = outp + (size_t)stok[mr0 + 8] * HD + n;
                    atomicAdd(op,     p * (acc[i][j][2] + bv[2 * j]));
                    atomicAdd(op + 1, p * (acc[i][j][3] + bv[2 * j + 1]));
                }
            }
        }
    }
}

// ---------------------------------------------------------------------------
extern "C" void kernel_launch(void* const* d_in, const int* in_sizes, int n_in,
                              void* d_out, int out_size) {
    const float* x  = (const float*)d_in[0];
    const float* Wr = (const float*)d_in[1];
    const float* br = (const float*)d_in[2];
    const float* W1 = (const float*)d_in[3];
    const float* b1 = (const float*)d_in[4];
    const float* W2 = (const float*)d_in[5];
    const float* b2 = (const float*)d_in[6];
    float* out = (float*)d_out;

    cudaFuncSetAttribute(k_gemm<0>, cudaFuncAttributeMaxDynamicSharedMemorySize, SMEM_SZ);
    cudaFuncSetAttribute(k_gemm<1>, cudaFuncAttributeMaxDynamicSharedMemorySize, SMEM_SZ);

    __half* gw1; cudaGetSymbolAddress((void**)&gw1, g_w1h);
    __half* gw2; cudaGetSymbolAddress((void**)&gw2, g_w2h);

    k_zero<<<2048, 256>>>(out, out_size / 4);
    k_router<<<TB / 8, 256>>>(x, Wr, br);
    // W1 [K=HD][N=FF] -> [FF][HD];  W2 [K=FF][N=HD] -> [HD][FF]
    dim3 t1(FF / 32, HD / 32, NE);
    k_cvt_t<<<t1, 256>>>(W1, gw1, HD, FF);
    dim3 t2(HD / 32, FF / 32, NE);
    k_cvt_t<<<t2, 256>>>(W2, gw2, FF, HD);
    dim3 g1(FF / BN, TB / BM, NE);   // (32, 64, 8)
    k_gemm<0><<<g1, GT, SMEM_SZ>>>(gw1, b1, nullptr);
    dim3 g2(HD / BN, TB / BM, NE);   // (8, 64, 8)
    k_gemm<1><<<g2, GT, SMEM_SZ>>>(gw2, b2, out);
}